// round 1
// baseline (speedup 1.0000x reference)
#include <cuda_runtime.h>
#include <cuda_bf16.h>
#include <mma.h>

using namespace nvcuda;

#define BB 4
#define CC 128
#define NN 4096
#define LDH 136   // bf16 tile leading dim (pad 8)
#define LDF 132   // fp32 tile leading dim (pad 4)

typedef wmma::fragment<wmma::matrix_a,16,16,16,__nv_bfloat16,wmma::row_major> FragA;
typedef wmma::fragment<wmma::matrix_b,16,16,16,__nv_bfloat16,wmma::col_major> FragBc;
typedef wmma::fragment<wmma::matrix_b,16,16,16,__nv_bfloat16,wmma::row_major> FragBr;
typedef wmma::fragment<wmma::accumulator,16,16,16,float> FragC;

// ---------------- device scratch (static allocation: allowed) ----------------
__device__ __nv_bfloat16 d_wqkv[3*CC*CC];
__device__ __nv_bfloat16 d_wproj[CC*CC];
__device__ float d_scl[BB*CC];   // per (b,c) scale  = rstd*gamma
__device__ float d_sht[BB*CC];   // per (b,c) shift  = beta - mean*rstd*gamma
__device__ __nv_bfloat16 d_q[BB*NN*CC];
__device__ __nv_bfloat16 d_k[BB*NN*CC];
__device__ __nv_bfloat16 d_v[BB*NN*CC];
__device__ __nv_bfloat16 d_o[BB*NN*CC];

// ---------------- K0: convert weights to bf16 ----------------
__global__ __launch_bounds__(256) void k_convert(const float* __restrict__ qkvw,
                                                 const float* __restrict__ projw) {
    int i = blockIdx.x*256 + threadIdx.x;
    if (i < 3*CC*CC) d_wqkv[i]  = __float2bfloat16(qkvw[i]);
    if (i < CC*CC)   d_wproj[i] = __float2bfloat16(projw[i]);
}

// ---------------- K1: GroupNorm stats -> per-channel scale/shift ----------------
__global__ __launch_bounds__(256) void k_gnstats(const float* __restrict__ x,
                                                 const float* __restrict__ nw,
                                                 const float* __restrict__ nb) {
    int b = blockIdx.x >> 3, g = blockIdx.x & 7;
    const float4* p = (const float4*)(x + ((size_t)(b*CC) + g*16)*NN);
    const int M4 = (16*NN)/4;   // contiguous span (channels contiguous within group)
    float s = 0.f, s2 = 0.f;
    for (int i = threadIdx.x; i < M4; i += 256) {
        float4 v = p[i];
        s  += v.x + v.y + v.z + v.w;
        s2 += v.x*v.x + v.y*v.y + v.z*v.z + v.w*v.w;
    }
    __shared__ float rs[8], rs2[8];
    #pragma unroll
    for (int o = 16; o; o >>= 1) {
        s  += __shfl_xor_sync(0xffffffffu, s,  o);
        s2 += __shfl_xor_sync(0xffffffffu, s2, o);
    }
    if ((threadIdx.x & 31) == 0) { rs[threadIdx.x>>5] = s; rs2[threadIdx.x>>5] = s2; }
    __syncthreads();
    __shared__ float smean, srstd;
    if (threadIdx.x == 0) {
        float ts = 0.f, ts2 = 0.f;
        #pragma unroll
        for (int i = 0; i < 8; i++) { ts += rs[i]; ts2 += rs2[i]; }
        const float M = 16.f*NN;
        float mean = ts / M;
        float var  = ts2 / M - mean*mean;
        smean = mean;
        srstd = rsqrtf(var + 1e-5f);
    }
    __syncthreads();
    if (threadIdx.x < 16) {
        int c = g*16 + threadIdx.x;
        float w = nw[c];
        d_scl[b*CC + c] = srstd * w;
        d_sht[b*CC + c] = nb[c] - smean * srstd * w;
    }
}

// ---------------- K2: fused normalize + QKV GEMM ----------------
// per CTA: one (b, n-tile of 128). A = normalized x^T tile [128n x 128c] (bf16),
// loop over 3 output tiles (q,k,v), B = qkv_w [o][c] as col-major K^T.
__global__ __launch_bounds__(256) void k_qkv(const float* __restrict__ x,
                                             const float* __restrict__ qkvb) {
    extern __shared__ char sm[];
    __nv_bfloat16* As = (__nv_bfloat16*)sm;                 // [128][LDH]
    __nv_bfloat16* Bs = As + 128*LDH;                       // [128][LDH]
    float*         Cs = (float*)(Bs + 128*LDH);             // [128][LDF]
    const int nt = blockIdx.x, b = blockIdx.y, tid = threadIdx.x;
    const int nbase = nt*128;

    // load + normalize + transpose A
    {
        int c = tid >> 1, nh = tid & 1;
        const float4* xp = (const float4*)(x + ((size_t)(b*CC) + c)*NN + nbase + nh*64);
        float sc = d_scl[b*CC + c], sh = d_sht[b*CC + c];
        #pragma unroll
        for (int i = 0; i < 16; i++) {
            float4 v = xp[i];
            int n = nh*64 + i*4;
            As[(n+0)*LDH + c] = __float2bfloat16(v.x*sc + sh);
            As[(n+1)*LDH + c] = __float2bfloat16(v.y*sc + sh);
            As[(n+2)*LDH + c] = __float2bfloat16(v.z*sc + sh);
            As[(n+3)*LDH + c] = __float2bfloat16(v.w*sc + sh);
        }
    }

    const int w = tid >> 5, wr = w >> 1, wc = w & 1;
    for (int ot = 0; ot < 3; ot++) {
        __syncthreads();
        // load B tile (row o, contiguous c)
        {
            int o = tid >> 1, ch = tid & 1;
            const uint2* wp = (const uint2*)(d_wqkv + (ot*128 + o)*CC + ch*64);
            uint2* dp = (uint2*)(Bs + o*LDH + ch*64);
            #pragma unroll
            for (int i = 0; i < 16; i++) dp[i] = wp[i];
        }
        __syncthreads();
        #pragma unroll
        for (int i = 0; i < 2; i++) {
            FragC acc[4];
            #pragma unroll
            for (int jj = 0; jj < 4; jj++) wmma::fill_fragment(acc[jj], 0.f);
            #pragma unroll
            for (int k = 0; k < 8; k++) {
                FragA a; wmma::load_matrix_sync(a, As + (wr*32 + i*16)*LDH + k*16, LDH);
                #pragma unroll
                for (int jj = 0; jj < 4; jj++) {
                    FragBc bfr; wmma::load_matrix_sync(bfr, Bs + (wc*64 + jj*16)*LDH + k*16, LDH);
                    wmma::mma_sync(acc[jj], a, bfr, acc[jj]);
                }
            }
            #pragma unroll
            for (int jj = 0; jj < 4; jj++)
                wmma::store_matrix_sync(Cs + (wr*32 + i*16)*LDF + wc*64 + jj*16, acc[jj], LDF, wmma::mem_row_major);
        }
        __syncthreads();
        // write out q/k/v bf16 with bias
        __nv_bfloat16* dst = (ot == 0) ? d_q : (ot == 1) ? d_k : d_v;
        {
            int n = tid >> 1, oh = tid & 1;
            __nv_bfloat16* op = dst + ((size_t)(b*NN) + nbase + n)*CC + oh*64;
            const float* cp = Cs + n*LDF + oh*64;
            const float* bp = qkvb + ot*128 + oh*64;
            #pragma unroll
            for (int i = 0; i < 64; i++) op[i] = __float2bfloat16(cp[i] + bp[i]);
        }
    }
}

// ---------------- K3: attention (no-max softmax, unnormalized accumulate) ----------------
__global__ __launch_bounds__(256) void k_attn() {
    extern __shared__ char sm[];
    __nv_bfloat16* Qs = (__nv_bfloat16*)sm;        // [128][LDH]
    __nv_bfloat16* Ks = Qs + 128*LDH;
    __nv_bfloat16* Vs = Ks + 128*LDH;
    __nv_bfloat16* Ps = Vs + 128*LDH;
    float*         Ss = (float*)(Ps + 128*LDH);    // [128][LDF], reused for O at end
    float*       lsum = Ss + 128*LDF;              // [128]
    float*      lpart = lsum + 128;                // [256]

    const int qt = blockIdx.x, b = blockIdx.y, tid = threadIdx.x;
    const int w = tid >> 5, wr = w >> 1, wc = w & 1;
    const float scale = 0.08838834764831845f;  // 1/sqrt(128)

    // load Q tile (vectorized)
    {
        const uint2* qg = (const uint2*)(d_q + ((size_t)(b*NN) + qt*128)*CC);
        for (int i = tid; i < 128*32; i += 256) {
            int r = i >> 5, c4 = (i & 31)*4;
            *(uint2*)&Qs[r*LDH + c4] = qg[r*32 + (i & 31)];
        }
    }
    if (tid < 128) lsum[tid] = 0.f;

    FragC o_acc[2][4];
    #pragma unroll
    for (int i = 0; i < 2; i++)
        #pragma unroll
        for (int jj = 0; jj < 4; jj++) wmma::fill_fragment(o_acc[i][jj], 0.f);

    for (int kt = 0; kt < 32; kt++) {
        __syncthreads();
        // load K, V tiles
        {
            const uint2* kg = (const uint2*)(d_k + ((size_t)(b*NN) + kt*128)*CC);
            const uint2* vg = (const uint2*)(d_v + ((size_t)(b*NN) + kt*128)*CC);
            for (int i = tid; i < 128*32; i += 256) {
                int r = i >> 5, cv = i & 31;
                *(uint2*)&Ks[r*LDH + cv*4] = kg[r*32 + cv];
                *(uint2*)&Vs[r*LDH + cv*4] = vg[r*32 + cv];
            }
        }
        __syncthreads();
        // S = Q K^T, exp, store to Ss
        #pragma unroll
        for (int i = 0; i < 2; i++) {
            FragC s4[4];
            #pragma unroll
            for (int jj = 0; jj < 4; jj++) wmma::fill_fragment(s4[jj], 0.f);
            #pragma unroll
            for (int k = 0; k < 8; k++) {
                FragA a; wmma::load_matrix_sync(a, Qs + (wr*32 + i*16)*LDH + k*16, LDH);
                #pragma unroll
                for (int jj = 0; jj < 4; jj++) {
                    FragBc bfr; wmma::load_matrix_sync(bfr, Ks + (wc*64 + jj*16)*LDH + k*16, LDH);
                    wmma::mma_sync(s4[jj], a, bfr, s4[jj]);
                }
            }
            #pragma unroll
            for (int jj = 0; jj < 4; jj++) {
                #pragma unroll
                for (int e = 0; e < s4[jj].num_elements; e++)
                    s4[jj].x[e] = __expf(s4[jj].x[e]*scale);
                wmma::store_matrix_sync(Ss + (wr*32 + i*16)*LDF + wc*64 + jj*16, s4[jj], LDF, wmma::mem_row_major);
            }
        }
        __syncthreads();
        // P = bf16(exp), accumulate row sums
        {
            int r = tid >> 1, hh = tid & 1;
            const float* sp = Ss + r*LDF + hh*64;
            __nv_bfloat16* pp = Ps + r*LDH + hh*64;
            float s = 0.f;
            #pragma unroll
            for (int i = 0; i < 32; i++) {
                float v0 = sp[2*i], v1 = sp[2*i+1];
                *(__nv_bfloat162*)&pp[2*i] = __floats2bfloat162_rn(v0, v1);
                s += v0 + v1;
            }
            lpart[tid] = s;
        }
        __syncthreads();
        if (tid < 128) lsum[tid] += lpart[tid*2] + lpart[tid*2 + 1];
        // O += P V
        #pragma unroll
        for (int i = 0; i < 2; i++) {
            #pragma unroll
            for (int k = 0; k < 8; k++) {
                FragA a; wmma::load_matrix_sync(a, Ps + (wr*32 + i*16)*LDH + k*16, LDH);
                #pragma unroll
                for (int jj = 0; jj < 4; jj++) {
                    FragBr bfr; wmma::load_matrix_sync(bfr, Vs + (k*16)*LDH + wc*64 + jj*16, LDH);
                    wmma::mma_sync(o_acc[i][jj], a, bfr, o_acc[i][jj]);
                }
            }
        }
    }
    __syncthreads();
    // stage O to smem, then normalize + write bf16
    #pragma unroll
    for (int i = 0; i < 2; i++)
        #pragma unroll
        for (int jj = 0; jj < 4; jj++)
            wmma::store_matrix_sync(Ss + (wr*32 + i*16)*LDF + wc*64 + jj*16, o_acc[i][jj], LDF, wmma::mem_row_major);
    __syncthreads();
    {
        int r = tid >> 1, hh = tid & 1;
        float inv = 1.f / lsum[r];
        __nv_bfloat16* og = d_o + ((size_t)(b*NN) + qt*128 + r)*CC + hh*64;
        const float* sp = Ss + r*LDF + hh*64;
        #pragma unroll
        for (int i = 0; i < 64; i++) og[i] = __float2bfloat16(sp[i]*inv);
    }
}

// ---------------- K4: proj GEMM + bias + residual ----------------
__global__ __launch_bounds__(256) void k_proj(const float* __restrict__ x,
                                              const float* __restrict__ projb,
                                              float* __restrict__ out) {
    extern __shared__ char sm[];
    __nv_bfloat16* As = (__nv_bfloat16*)sm;                 // [128n][LDH]
    __nv_bfloat16* Bs = As + 128*LDH;                       // [128o][LDH]
    float*         Cs = (float*)(Bs + 128*LDH);             // [128n][LDF]
    const int nt = blockIdx.x, b = blockIdx.y, tid = threadIdx.x;
    const int nbase = nt*128;

    // load A = attention output tile [n][c] bf16
    {
        const uint2* ag = (const uint2*)(d_o + ((size_t)(b*NN) + nbase)*CC);
        for (int i = tid; i < 128*32; i += 256) {
            int r = i >> 5, cv = i & 31;
            *(uint2*)&As[r*LDH + cv*4] = ag[r*32 + cv];
        }
    }
    // load B = proj_w [o][c]
    {
        int o = tid >> 1, ch = tid & 1;
        const uint2* wp = (const uint2*)(d_wproj + o*CC + ch*64);
        uint2* dp = (uint2*)(Bs + o*LDH + ch*64);
        #pragma unroll
        for (int i = 0; i < 16; i++) dp[i] = wp[i];
    }
    __syncthreads();

    const int w = tid >> 5, wr = w >> 1, wc = w & 1;
    #pragma unroll
    for (int i = 0; i < 2; i++) {
        FragC acc[4];
        #pragma unroll
        for (int jj = 0; jj < 4; jj++) wmma::fill_fragment(acc[jj], 0.f);
        #pragma unroll
        for (int k = 0; k < 8; k++) {
            FragA a; wmma::load_matrix_sync(a, As + (wr*32 + i*16)*LDH + k*16, LDH);
            #pragma unroll
            for (int jj = 0; jj < 4; jj++) {
                FragBc bfr; wmma::load_matrix_sync(bfr, Bs + (wc*64 + jj*16)*LDH + k*16, LDH);
                wmma::mma_sync(acc[jj], a, bfr, acc[jj]);
            }
        }
        #pragma unroll
        for (int jj = 0; jj < 4; jj++)
            wmma::store_matrix_sync(Cs + (wr*32 + i*16)*LDF + wc*64 + jj*16, acc[jj], LDF, wmma::mem_row_major);
    }
    __syncthreads();
    // out[b][c][n] = x + proj + bias  (transposed write, coalesced over n)
    {
        int c = tid >> 1, nh = tid & 1;
        const float* xp = x + ((size_t)(b*CC) + c)*NN + nbase + nh*64;
        float* op = out + ((size_t)(b*CC) + c)*NN + nbase + nh*64;
        float pb = projb[c];
        #pragma unroll
        for (int i = 0; i < 64; i++)
            op[i] = xp[i] + pb + Cs[(nh*64 + i)*LDF + c];
    }
}

// ---------------- launcher ----------------
extern "C" void kernel_launch(void* const* d_in, const int* in_sizes, int n_in,
                              void* d_out, int out_size) {
    const float* x     = (const float*)d_in[0];
    const float* nw    = (const float*)d_in[1];
    const float* nb    = (const float*)d_in[2];
    const float* qkvw  = (const float*)d_in[3];
    const float* qkvb  = (const float*)d_in[4];
    const float* projw = (const float*)d_in[5];
    const float* projb = (const float*)d_in[6];
    float* out = (float*)d_out;

    const int SM_GEMM = 2*128*LDH*2 + 128*LDF*4;                       // 137216
    const int SM_ATTN = 4*128*LDH*2 + 128*LDF*4 + (128 + 256)*4;       // 208384

    cudaFuncSetAttribute(k_qkv,  cudaFuncAttributeMaxDynamicSharedMemorySize, SM_GEMM);
    cudaFuncSetAttribute(k_attn, cudaFuncAttributeMaxDynamicSharedMemorySize, SM_ATTN);
    cudaFuncSetAttribute(k_proj, cudaFuncAttributeMaxDynamicSharedMemorySize, SM_GEMM);

    k_convert<<<192, 256>>>(qkvw, projw);
    k_gnstats<<<32, 256>>>(x, nw, nb);
    k_qkv<<<dim3(32, BB), 256, SM_GEMM>>>(x, qkvb);
    k_attn<<<dim3(32, BB), 256, SM_ATTN>>>();
    k_proj<<<dim3(32, BB), 256, SM_GEMM>>>(x, projb, out);
}

// round 2
// speedup vs baseline: 1.0183x; 1.0183x over previous
#include <cuda_runtime.h>
#include <cuda_bf16.h>
#include <mma.h>

using namespace nvcuda;

#define BB 4
#define CC 128
#define NN 4096
#define LDH 136   // bf16 tile leading dim (pad 8)
#define LDF 132   // fp32 tile leading dim (pad 4)

typedef wmma::fragment<wmma::matrix_a,16,16,16,__nv_bfloat16,wmma::row_major> FragA;
typedef wmma::fragment<wmma::matrix_b,16,16,16,__nv_bfloat16,wmma::col_major> FragBc;
typedef wmma::fragment<wmma::matrix_b,16,16,16,__nv_bfloat16,wmma::row_major> FragBr;
typedef wmma::fragment<wmma::accumulator,16,16,16,float> FragC;

// ---------------- device scratch (static allocation: allowed) ----------------
__device__ __nv_bfloat16 d_wqkv[3*CC*CC];
__device__ __nv_bfloat16 d_wproj[CC*CC];
__device__ float d_scl[BB*CC];   // per (b,c) scale  = rstd*gamma
__device__ float d_sht[BB*CC];   // per (b,c) shift  = beta - mean*rstd*gamma
__device__ __nv_bfloat16 d_q[BB*NN*CC];
__device__ __nv_bfloat16 d_k[BB*NN*CC];
__device__ __nv_bfloat16 d_v[BB*NN*CC];
__device__ __nv_bfloat16 d_o[BB*NN*CC];

// ---------------- K0: convert weights to bf16 ----------------
__global__ __launch_bounds__(256) void k_convert(const float* __restrict__ qkvw,
                                                 const float* __restrict__ projw) {
    int i = blockIdx.x*256 + threadIdx.x;
    if (i < 3*CC*CC) d_wqkv[i]  = __float2bfloat16(qkvw[i]);
    if (i < CC*CC)   d_wproj[i] = __float2bfloat16(projw[i]);
}

// ---------------- K1: GroupNorm stats -> per-channel scale/shift ----------------
__global__ __launch_bounds__(256) void k_gnstats(const float* __restrict__ x,
                                                 const float* __restrict__ nw,
                                                 const float* __restrict__ nb) {
    int b = blockIdx.x >> 3, g = blockIdx.x & 7;
    const float4* p = (const float4*)(x + ((size_t)(b*CC) + g*16)*NN);
    const int M4 = (16*NN)/4;   // contiguous span (channels contiguous within group)
    float s = 0.f, s2 = 0.f;
    for (int i = threadIdx.x; i < M4; i += 256) {
        float4 v = p[i];
        s  += v.x + v.y + v.z + v.w;
        s2 += v.x*v.x + v.y*v.y + v.z*v.z + v.w*v.w;
    }
    __shared__ float rs[8], rs2[8];
    #pragma unroll
    for (int o = 16; o; o >>= 1) {
        s  += __shfl_xor_sync(0xffffffffu, s,  o);
        s2 += __shfl_xor_sync(0xffffffffu, s2, o);
    }
    if ((threadIdx.x & 31) == 0) { rs[threadIdx.x>>5] = s; rs2[threadIdx.x>>5] = s2; }
    __syncthreads();
    __shared__ float smean, srstd;
    if (threadIdx.x == 0) {
        float ts = 0.f, ts2 = 0.f;
        #pragma unroll
        for (int i = 0; i < 8; i++) { ts += rs[i]; ts2 += rs2[i]; }
        const float M = 16.f*NN;
        float mean = ts / M;
        float var  = ts2 / M - mean*mean;
        smean = mean;
        srstd = rsqrtf(var + 1e-5f);
    }
    __syncthreads();
    if (threadIdx.x < 16) {
        int c = g*16 + threadIdx.x;
        float w = nw[c];
        d_scl[b*CC + c] = srstd * w;
        d_sht[b*CC + c] = nb[c] - smean * srstd * w;
    }
}

// ---------------- K2: fused normalize + QKV GEMM ----------------
// per CTA: one (b, n-tile of 128). A = normalized x^T tile [128n x 128c] (bf16),
// loop over 3 output tiles (q,k,v), B = qkv_w [o][c] as col-major K^T.
__global__ __launch_bounds__(256) void k_qkv(const float* __restrict__ x,
                                             const float* __restrict__ qkvb) {
    extern __shared__ char sm[];
    __nv_bfloat16* As = (__nv_bfloat16*)sm;                 // [128][LDH]
    __nv_bfloat16* Bs = As + 128*LDH;                       // [128][LDH]
    float*         Cs = (float*)(Bs + 128*LDH);             // [128][LDF]
    const int nt = blockIdx.x, b = blockIdx.y, tid = threadIdx.x;
    const int nbase = nt*128;

    // load + normalize + transpose A
    {
        int c = tid >> 1, nh = tid & 1;
        const float4* xp = (const float4*)(x + ((size_t)(b*CC) + c)*NN + nbase + nh*64);
        float sc = d_scl[b*CC + c], sh = d_sht[b*CC + c];
        #pragma unroll
        for (int i = 0; i < 16; i++) {
            float4 v = xp[i];
            int n = nh*64 + i*4;
            As[(n+0)*LDH + c] = __float2bfloat16(v.x*sc + sh);
            As[(n+1)*LDH + c] = __float2bfloat16(v.y*sc + sh);
            As[(n+2)*LDH + c] = __float2bfloat16(v.z*sc + sh);
            As[(n+3)*LDH + c] = __float2bfloat16(v.w*sc + sh);
        }
    }

    const int w = tid >> 5, wr = w >> 1, wc = w & 1;
    for (int ot = 0; ot < 3; ot++) {
        __syncthreads();
        // load B tile (row o, contiguous c)
        {
            int o = tid >> 1, ch = tid & 1;
            const uint2* wp = (const uint2*)(d_wqkv + (ot*128 + o)*CC + ch*64);
            uint2* dp = (uint2*)(Bs + o*LDH + ch*64);
            #pragma unroll
            for (int i = 0; i < 16; i++) dp[i] = wp[i];
        }
        __syncthreads();
        #pragma unroll
        for (int i = 0; i < 2; i++) {
            FragC acc[4];
            #pragma unroll
            for (int jj = 0; jj < 4; jj++) wmma::fill_fragment(acc[jj], 0.f);
            #pragma unroll
            for (int k = 0; k < 8; k++) {
                FragA a; wmma::load_matrix_sync(a, As + (wr*32 + i*16)*LDH + k*16, LDH);
                #pragma unroll
                for (int jj = 0; jj < 4; jj++) {
                    FragBc bfr; wmma::load_matrix_sync(bfr, Bs + (wc*64 + jj*16)*LDH + k*16, LDH);
                    wmma::mma_sync(acc[jj], a, bfr, acc[jj]);
                }
            }
            #pragma unroll
            for (int jj = 0; jj < 4; jj++)
                wmma::store_matrix_sync(Cs + (wr*32 + i*16)*LDF + wc*64 + jj*16, acc[jj], LDF, wmma::mem_row_major);
        }
        __syncthreads();
        // write out q/k/v bf16 with bias
        __nv_bfloat16* dst = (ot == 0) ? d_q : (ot == 1) ? d_k : d_v;
        {
            int n = tid >> 1, oh = tid & 1;
            __nv_bfloat16* op = dst + ((size_t)(b*NN) + nbase + n)*CC + oh*64;
            const float* cp = Cs + n*LDF + oh*64;
            const float* bp = qkvb + ot*128 + oh*64;
            #pragma unroll
            for (int i = 0; i < 64; i++) op[i] = __float2bfloat16(cp[i] + bp[i]);
        }
    }
}

// ---------------- K3: attention (no-max softmax, unnormalized accumulate) ----------------
__global__ __launch_bounds__(256) void k_attn() {
    extern __shared__ char sm[];
    __nv_bfloat16* Qs = (__nv_bfloat16*)sm;        // [128][LDH]
    __nv_bfloat16* Ks = Qs + 128*LDH;
    __nv_bfloat16* Vs = Ks + 128*LDH;
    __nv_bfloat16* Ps = Vs + 128*LDH;
    float*         Ss = (float*)(Ps + 128*LDH);    // [128][LDF], reused for O at end
    float*       lsum = Ss + 128*LDF;              // [128]
    float*      lpart = lsum + 128;                // [256]

    const int qt = blockIdx.x, b = blockIdx.y, tid = threadIdx.x;
    const int w = tid >> 5, wr = w >> 1, wc = w & 1;
    const float scale = 0.08838834764831845f;  // 1/sqrt(128)

    // load Q tile (vectorized)
    {
        const uint2* qg = (const uint2*)(d_q + ((size_t)(b*NN) + qt*128)*CC);
        for (int i = tid; i < 128*32; i += 256) {
            int r = i >> 5, c4 = (i & 31)*4;
            *(uint2*)&Qs[r*LDH + c4] = qg[r*32 + (i & 31)];
        }
    }
    if (tid < 128) lsum[tid] = 0.f;

    FragC o_acc[2][4];
    #pragma unroll
    for (int i = 0; i < 2; i++)
        #pragma unroll
        for (int jj = 0; jj < 4; jj++) wmma::fill_fragment(o_acc[i][jj], 0.f);

    for (int kt = 0; kt < 32; kt++) {
        __syncthreads();
        // load K, V tiles
        {
            const uint2* kg = (const uint2*)(d_k + ((size_t)(b*NN) + kt*128)*CC);
            const uint2* vg = (const uint2*)(d_v + ((size_t)(b*NN) + kt*128)*CC);
            for (int i = tid; i < 128*32; i += 256) {
                int r = i >> 5, cv = i & 31;
                *(uint2*)&Ks[r*LDH + cv*4] = kg[r*32 + cv];
                *(uint2*)&Vs[r*LDH + cv*4] = vg[r*32 + cv];
            }
        }
        __syncthreads();
        // S = Q K^T, exp, store to Ss
        #pragma unroll
        for (int i = 0; i < 2; i++) {
            FragC s4[4];
            #pragma unroll
            for (int jj = 0; jj < 4; jj++) wmma::fill_fragment(s4[jj], 0.f);
            #pragma unroll
            for (int k = 0; k < 8; k++) {
                FragA a; wmma::load_matrix_sync(a, Qs + (wr*32 + i*16)*LDH + k*16, LDH);
                #pragma unroll
                for (int jj = 0; jj < 4; jj++) {
                    FragBc bfr; wmma::load_matrix_sync(bfr, Ks + (wc*64 + jj*16)*LDH + k*16, LDH);
                    wmma::mma_sync(s4[jj], a, bfr, s4[jj]);
                }
            }
            #pragma unroll
            for (int jj = 0; jj < 4; jj++) {
                #pragma unroll
                for (int e = 0; e < s4[jj].num_elements; e++)
                    s4[jj].x[e] = __expf(s4[jj].x[e]*scale);
                wmma::store_matrix_sync(Ss + (wr*32 + i*16)*LDF + wc*64 + jj*16, s4[jj], LDF, wmma::mem_row_major);
            }
        }
        __syncthreads();
        // P = bf16(exp), accumulate row sums
        {
            int r = tid >> 1, hh = tid & 1;
            const float* sp = Ss + r*LDF + hh*64;
            __nv_bfloat16* pp = Ps + r*LDH + hh*64;
            float s = 0.f;
            #pragma unroll
            for (int i = 0; i < 32; i++) {
                float v0 = sp[2*i], v1 = sp[2*i+1];
                *(__nv_bfloat162*)&pp[2*i] = __floats2bfloat162_rn(v0, v1);
                s += v0 + v1;
            }
            lpart[tid] = s;
        }
        __syncthreads();
        if (tid < 128) lsum[tid] += lpart[tid*2] + lpart[tid*2 + 1];
        // O += P V
        #pragma unroll
        for (int i = 0; i < 2; i++) {
            #pragma unroll
            for (int k = 0; k < 8; k++) {
                FragA a; wmma::load_matrix_sync(a, Ps + (wr*32 + i*16)*LDH + k*16, LDH);
                #pragma unroll
                for (int jj = 0; jj < 4; jj++) {
                    FragBr bfr; wmma::load_matrix_sync(bfr, Vs + (k*16)*LDH + wc*64 + jj*16, LDH);
                    wmma::mma_sync(o_acc[i][jj], a, bfr, o_acc[i][jj]);
                }
            }
        }
    }
    __syncthreads();
    // stage O to smem, then normalize + write bf16
    #pragma unroll
    for (int i = 0; i < 2; i++)
        #pragma unroll
        for (int jj = 0; jj < 4; jj++)
            wmma::store_matrix_sync(Ss + (wr*32 + i*16)*LDF + wc*64 + jj*16, o_acc[i][jj], LDF, wmma::mem_row_major);
    __syncthreads();
    {
        int r = tid >> 1, hh = tid & 1;
        float inv = 1.f / lsum[r];
        __nv_bfloat16* og = d_o + ((size_t)(b*NN) + qt*128 + r)*CC + hh*64;
        const float* sp = Ss + r*LDF + hh*64;
        #pragma unroll
        for (int i = 0; i < 64; i++) og[i] = __float2bfloat16(sp[i]*inv);
    }
}

// ---------------- K4: proj GEMM + bias + residual ----------------
__global__ __launch_bounds__(256) void k_proj(const float* __restrict__ x,
                                              const float* __restrict__ projb,
                                              float* __restrict__ out) {
    extern __shared__ char sm[];
    __nv_bfloat16* As = (__nv_bfloat16*)sm;                 // [128n][LDH]
    __nv_bfloat16* Bs = As + 128*LDH;                       // [128o][LDH]
    float*         Cs = (float*)(Bs + 128*LDH);             // [128n][LDF]
    const int nt = blockIdx.x, b = blockIdx.y, tid = threadIdx.x;
    const int nbase = nt*128;

    // load A = attention output tile [n][c] bf16
    {
        const uint2* ag = (const uint2*)(d_o + ((size_t)(b*NN) + nbase)*CC);
        for (int i = tid; i < 128*32; i += 256) {
            int r = i >> 5, cv = i & 31;
            *(uint2*)&As[r*LDH + cv*4] = ag[r*32 + cv];
        }
    }
    // load B = proj_w [o][c]
    {
        int o = tid >> 1, ch = tid & 1;
        const uint2* wp = (const uint2*)(d_wproj + o*CC + ch*64);
        uint2* dp = (uint2*)(Bs + o*LDH + ch*64);
        #pragma unroll
        for (int i = 0; i < 16; i++) dp[i] = wp[i];
    }
    __syncthreads();

    const int w = tid >> 5, wr = w >> 1, wc = w & 1;
    #pragma unroll
    for (int i = 0; i < 2; i++) {
        FragC acc[4];
        #pragma unroll
        for (int jj = 0; jj < 4; jj++) wmma::fill_fragment(acc[jj], 0.f);
        #pragma unroll
        for (int k = 0; k < 8; k++) {
            FragA a; wmma::load_matrix_sync(a, As + (wr*32 + i*16)*LDH + k*16, LDH);
            #pragma unroll
            for (int jj = 0; jj < 4; jj++) {
                FragBc bfr; wmma::load_matrix_sync(bfr, Bs + (wc*64 + jj*16)*LDH + k*16, LDH);
                wmma::mma_sync(acc[jj], a, bfr, acc[jj]);
            }
        }
        #pragma unroll
        for (int jj = 0; jj < 4; jj++)
            wmma::store_matrix_sync(Cs + (wr*32 + i*16)*LDF + wc*64 + jj*16, acc[jj], LDF, wmma::mem_row_major);
    }
    __syncthreads();
    // out[b][c][n] = x + proj + bias  (transposed write, coalesced over n)
    {
        int c = tid >> 1, nh = tid & 1;
        const float* xp = x + ((size_t)(b*CC) + c)*NN + nbase + nh*64;
        float* op = out + ((size_t)(b*CC) + c)*NN + nbase + nh*64;
        float pb = projb[c];
        #pragma unroll
        for (int i = 0; i < 64; i++)
            op[i] = xp[i] + pb + Cs[(nh*64 + i)*LDF + c];
    }
}

// ---------------- launcher ----------------
extern "C" void kernel_launch(void* const* d_in, const int* in_sizes, int n_in,
                              void* d_out, int out_size) {
    const float* x     = (const float*)d_in[0];
    const float* nw    = (const float*)d_in[1];
    const float* nb    = (const float*)d_in[2];
    const float* qkvw  = (const float*)d_in[3];
    const float* qkvb  = (const float*)d_in[4];
    const float* projw = (const float*)d_in[5];
    const float* projb = (const float*)d_in[6];
    float* out = (float*)d_out;

    const int SM_GEMM = 2*128*LDH*2 + 128*LDF*4;                       // 137216
    const int SM_ATTN = 4*128*LDH*2 + 128*LDF*4 + (128 + 256)*4;       // 208384

    cudaFuncSetAttribute(k_qkv,  cudaFuncAttributeMaxDynamicSharedMemorySize, SM_GEMM);
    cudaFuncSetAttribute(k_attn, cudaFuncAttributeMaxDynamicSharedMemorySize, SM_ATTN);
    cudaFuncSetAttribute(k_proj, cudaFuncAttributeMaxDynamicSharedMemorySize, SM_GEMM);

    k_convert<<<192, 256>>>(qkvw, projw);
    k_gnstats<<<32, 256>>>(x, nw, nb);
    k_qkv<<<dim3(32, BB), 256, SM_GEMM>>>(x, qkvb);
    k_attn<<<dim3(32, BB), 256, SM_ATTN>>>();
    k_proj<<<dim3(32, BB), 256, SM_GEMM>>>(x, projb, out);
}

// round 3
// speedup vs baseline: 1.0217x; 1.0033x over previous
#include <cuda_runtime.h>
#include <cuda_bf16.h>
#include <mma.h>

using namespace nvcuda;

#define BB 4
#define CC 128
#define NN 4096
#define LDH 136   // bf16 tile leading dim (pad 8)
#define LDF 132   // fp32 tile leading dim (pad 4)

typedef wmma::fragment<wmma::matrix_a,16,16,16,__nv_bfloat16,wmma::row_major> FragA;
typedef wmma::fragment<wmma::matrix_b,16,16,16,__nv_bfloat16,wmma::col_major> FragBc;
typedef wmma::fragment<wmma::matrix_b,16,16,16,__nv_bfloat16,wmma::row_major> FragBr;
typedef wmma::fragment<wmma::accumulator,16,16,16,float> FragC;

// ---------------- device scratch (static allocation: allowed) ----------------
__device__ __nv_bfloat16 d_wqkv[3*CC*CC];
__device__ __nv_bfloat16 d_wproj[CC*CC];
__device__ float d_scl[BB*CC];   // per (b,c) scale  = rstd*gamma
__device__ float d_sht[BB*CC];   // per (b,c) shift  = beta - mean*rstd*gamma
__device__ __nv_bfloat16 d_q[BB*NN*CC];
__device__ __nv_bfloat16 d_k[BB*NN*CC];
__device__ __nv_bfloat16 d_v[BB*NN*CC];
__device__ __nv_bfloat16 d_o[BB*NN*CC];

// ---------------- K0: convert weights to bf16 ----------------
__global__ __launch_bounds__(256) void k_convert(const float* __restrict__ qkvw,
                                                 const float* __restrict__ projw) {
    int i = blockIdx.x*256 + threadIdx.x;
    if (i < 3*CC*CC) d_wqkv[i]  = __float2bfloat16(qkvw[i]);
    if (i < CC*CC)   d_wproj[i] = __float2bfloat16(projw[i]);
}

// ---------------- K1: GroupNorm stats -> per-channel scale/shift ----------------
__global__ __launch_bounds__(256) void k_gnstats(const float* __restrict__ x,
                                                 const float* __restrict__ nw,
                                                 const float* __restrict__ nb) {
    int b = blockIdx.x >> 3, g = blockIdx.x & 7;
    const float4* p = (const float4*)(x + ((size_t)(b*CC) + g*16)*NN);
    const int M4 = (16*NN)/4;   // contiguous span (channels contiguous within group)
    float s = 0.f, s2 = 0.f;
    for (int i = threadIdx.x; i < M4; i += 256) {
        float4 v = p[i];
        s  += v.x + v.y + v.z + v.w;
        s2 += v.x*v.x + v.y*v.y + v.z*v.z + v.w*v.w;
    }
    __shared__ float rs[8], rs2[8];
    #pragma unroll
    for (int o = 16; o; o >>= 1) {
        s  += __shfl_xor_sync(0xffffffffu, s,  o);
        s2 += __shfl_xor_sync(0xffffffffu, s2, o);
    }
    if ((threadIdx.x & 31) == 0) { rs[threadIdx.x>>5] = s; rs2[threadIdx.x>>5] = s2; }
    __syncthreads();
    __shared__ float smean, srstd;
    if (threadIdx.x == 0) {
        float ts = 0.f, ts2 = 0.f;
        #pragma unroll
        for (int i = 0; i < 8; i++) { ts += rs[i]; ts2 += rs2[i]; }
        const float M = 16.f*NN;
        float mean = ts / M;
        float var  = ts2 / M - mean*mean;
        smean = mean;
        srstd = rsqrtf(var + 1e-5f);
    }
    __syncthreads();
    if (threadIdx.x < 16) {
        int c = g*16 + threadIdx.x;
        float w = nw[c];
        d_scl[b*CC + c] = srstd * w;
        d_sht[b*CC + c] = nb[c] - smean * srstd * w;
    }
}

// ---------------- K2: fused normalize + QKV GEMM ----------------
// per CTA: one (b, n-tile of 128). A = normalized x^T tile [128n x 128c] (bf16),
// loop over 3 output tiles (q,k,v), B = qkv_w [o][c] as col-major K^T.
__global__ __launch_bounds__(256) void k_qkv(const float* __restrict__ x,
                                             const float* __restrict__ qkvb) {
    extern __shared__ char sm[];
    __nv_bfloat16* As = (__nv_bfloat16*)sm;                 // [128][LDH]
    __nv_bfloat16* Bs = As + 128*LDH;                       // [128][LDH]
    float*         Cs = (float*)(Bs + 128*LDH);             // [128][LDF]
    const int nt = blockIdx.x, b = blockIdx.y, tid = threadIdx.x;
    const int nbase = nt*128;

    // load + normalize + transpose A
    {
        int c = tid >> 1, nh = tid & 1;
        const float4* xp = (const float4*)(x + ((size_t)(b*CC) + c)*NN + nbase + nh*64);
        float sc = d_scl[b*CC + c], sh = d_sht[b*CC + c];
        #pragma unroll
        for (int i = 0; i < 16; i++) {
            float4 v = xp[i];
            int n = nh*64 + i*4;
            As[(n+0)*LDH + c] = __float2bfloat16(v.x*sc + sh);
            As[(n+1)*LDH + c] = __float2bfloat16(v.y*sc + sh);
            As[(n+2)*LDH + c] = __float2bfloat16(v.z*sc + sh);
            As[(n+3)*LDH + c] = __float2bfloat16(v.w*sc + sh);
        }
    }

    const int w = tid >> 5, wr = w >> 1, wc = w & 1;
    for (int ot = 0; ot < 3; ot++) {
        __syncthreads();
        // load B tile (row o, contiguous c)
        {
            int o = tid >> 1, ch = tid & 1;
            const uint2* wp = (const uint2*)(d_wqkv + (ot*128 + o)*CC + ch*64);
            uint2* dp = (uint2*)(Bs + o*LDH + ch*64);
            #pragma unroll
            for (int i = 0; i < 16; i++) dp[i] = wp[i];
        }
        __syncthreads();
        #pragma unroll
        for (int i = 0; i < 2; i++) {
            FragC acc[4];
            #pragma unroll
            for (int jj = 0; jj < 4; jj++) wmma::fill_fragment(acc[jj], 0.f);
            #pragma unroll
            for (int k = 0; k < 8; k++) {
                FragA a; wmma::load_matrix_sync(a, As + (wr*32 + i*16)*LDH + k*16, LDH);
                #pragma unroll
                for (int jj = 0; jj < 4; jj++) {
                    FragBc bfr; wmma::load_matrix_sync(bfr, Bs + (wc*64 + jj*16)*LDH + k*16, LDH);
                    wmma::mma_sync(acc[jj], a, bfr, acc[jj]);
                }
            }
            #pragma unroll
            for (int jj = 0; jj < 4; jj++)
                wmma::store_matrix_sync(Cs + (wr*32 + i*16)*LDF + wc*64 + jj*16, acc[jj], LDF, wmma::mem_row_major);
        }
        __syncthreads();
        // write out q/k/v bf16 with bias
        __nv_bfloat16* dst = (ot == 0) ? d_q : (ot == 1) ? d_k : d_v;
        {
            int n = tid >> 1, oh = tid & 1;
            __nv_bfloat16* op = dst + ((size_t)(b*NN) + nbase + n)*CC + oh*64;
            const float* cp = Cs + n*LDF + oh*64;
            const float* bp = qkvb + ot*128 + oh*64;
            #pragma unroll
            for (int i = 0; i < 64; i++) op[i] = __float2bfloat16(cp[i] + bp[i]);
        }
    }
}

// ---------------- K3: attention (no-max softmax, unnormalized accumulate) ----------------
__global__ __launch_bounds__(256) void k_attn() {
    extern __shared__ char sm[];
    __nv_bfloat16* Qs = (__nv_bfloat16*)sm;        // [128][LDH]
    __nv_bfloat16* Ks = Qs + 128*LDH;
    __nv_bfloat16* Vs = Ks + 128*LDH;
    __nv_bfloat16* Ps = Vs + 128*LDH;
    float*         Ss = (float*)(Ps + 128*LDH);    // [128][LDF], reused for O at end
    float*       lsum = Ss + 128*LDF;              // [128]
    float*      lpart = lsum + 128;                // [256]

    const int qt = blockIdx.x, b = blockIdx.y, tid = threadIdx.x;
    const int w = tid >> 5, wr = w >> 1, wc = w & 1;
    const float scale = 0.08838834764831845f;  // 1/sqrt(128)

    // load Q tile (vectorized)
    {
        const uint2* qg = (const uint2*)(d_q + ((size_t)(b*NN) + qt*128)*CC);
        for (int i = tid; i < 128*32; i += 256) {
            int r = i >> 5, c4 = (i & 31)*4;
            *(uint2*)&Qs[r*LDH + c4] = qg[r*32 + (i & 31)];
        }
    }
    if (tid < 128) lsum[tid] = 0.f;

    FragC o_acc[2][4];
    #pragma unroll
    for (int i = 0; i < 2; i++)
        #pragma unroll
        for (int jj = 0; jj < 4; jj++) wmma::fill_fragment(o_acc[i][jj], 0.f);

    for (int kt = 0; kt < 32; kt++) {
        __syncthreads();
        // load K, V tiles
        {
            const uint2* kg = (const uint2*)(d_k + ((size_t)(b*NN) + kt*128)*CC);
            const uint2* vg = (const uint2*)(d_v + ((size_t)(b*NN) + kt*128)*CC);
            for (int i = tid; i < 128*32; i += 256) {
                int r = i >> 5, cv = i & 31;
                *(uint2*)&Ks[r*LDH + cv*4] = kg[r*32 + cv];
                *(uint2*)&Vs[r*LDH + cv*4] = vg[r*32 + cv];
            }
        }
        __syncthreads();
        // S = Q K^T, exp, store to Ss
        #pragma unroll
        for (int i = 0; i < 2; i++) {
            FragC s4[4];
            #pragma unroll
            for (int jj = 0; jj < 4; jj++) wmma::fill_fragment(s4[jj], 0.f);
            #pragma unroll
            for (int k = 0; k < 8; k++) {
                FragA a; wmma::load_matrix_sync(a, Qs + (wr*32 + i*16)*LDH + k*16, LDH);
                #pragma unroll
                for (int jj = 0; jj < 4; jj++) {
                    FragBc bfr; wmma::load_matrix_sync(bfr, Ks + (wc*64 + jj*16)*LDH + k*16, LDH);
                    wmma::mma_sync(s4[jj], a, bfr, s4[jj]);
                }
            }
            #pragma unroll
            for (int jj = 0; jj < 4; jj++) {
                #pragma unroll
                for (int e = 0; e < s4[jj].num_elements; e++)
                    s4[jj].x[e] = __expf(s4[jj].x[e]*scale);
                wmma::store_matrix_sync(Ss + (wr*32 + i*16)*LDF + wc*64 + jj*16, s4[jj], LDF, wmma::mem_row_major);
            }
        }
        __syncthreads();
        // P = bf16(exp), accumulate row sums
        {
            int r = tid >> 1, hh = tid & 1;
            const float* sp = Ss + r*LDF + hh*64;
            __nv_bfloat16* pp = Ps + r*LDH + hh*64;
            float s = 0.f;
            #pragma unroll
            for (int i = 0; i < 32; i++) {
                float v0 = sp[2*i], v1 = sp[2*i+1];
                *(__nv_bfloat162*)&pp[2*i] = __floats2bfloat162_rn(v0, v1);
                s += v0 + v1;
            }
            lpart[tid] = s;
        }
        __syncthreads();
        if (tid < 128) lsum[tid] += lpart[tid*2] + lpart[tid*2 + 1];
        // O += P V
        #pragma unroll
        for (int i = 0; i < 2; i++) {
            #pragma unroll
            for (int k = 0; k < 8; k++) {
                FragA a; wmma::load_matrix_sync(a, Ps + (wr*32 + i*16)*LDH + k*16, LDH);
                #pragma unroll
                for (int jj = 0; jj < 4; jj++) {
                    FragBr bfr; wmma::load_matrix_sync(bfr, Vs + (k*16)*LDH + wc*64 + jj*16, LDH);
                    wmma::mma_sync(o_acc[i][jj], a, bfr, o_acc[i][jj]);
                }
            }
        }
    }
    __syncthreads();
    // stage O to smem, then normalize + write bf16
    #pragma unroll
    for (int i = 0; i < 2; i++)
        #pragma unroll
        for (int jj = 0; jj < 4; jj++)
            wmma::store_matrix_sync(Ss + (wr*32 + i*16)*LDF + wc*64 + jj*16, o_acc[i][jj], LDF, wmma::mem_row_major);
    __syncthreads();
    {
        int r = tid >> 1, hh = tid & 1;
        float inv = 1.f / lsum[r];
        __nv_bfloat16* og = d_o + ((size_t)(b*NN) + qt*128 + r)*CC + hh*64;
        const float* sp = Ss + r*LDF + hh*64;
        #pragma unroll
        for (int i = 0; i < 64; i++) og[i] = __float2bfloat16(sp[i]*inv);
    }
}

// ---------------- K4: proj GEMM + bias + residual ----------------
__global__ __launch_bounds__(256) void k_proj(const float* __restrict__ x,
                                              const float* __restrict__ projb,
                                              float* __restrict__ out) {
    extern __shared__ char sm[];
    __nv_bfloat16* As = (__nv_bfloat16*)sm;                 // [128n][LDH]
    __nv_bfloat16* Bs = As + 128*LDH;                       // [128o][LDH]
    float*         Cs = (float*)(Bs + 128*LDH);             // [128n][LDF]
    const int nt = blockIdx.x, b = blockIdx.y, tid = threadIdx.x;
    const int nbase = nt*128;

    // load A = attention output tile [n][c] bf16
    {
        const uint2* ag = (const uint2*)(d_o + ((size_t)(b*NN) + nbase)*CC);
        for (int i = tid; i < 128*32; i += 256) {
            int r = i >> 5, cv = i & 31;
            *(uint2*)&As[r*LDH + cv*4] = ag[r*32 + cv];
        }
    }
    // load B = proj_w [o][c]
    {
        int o = tid >> 1, ch = tid & 1;
        const uint2* wp = (const uint2*)(d_wproj + o*CC + ch*64);
        uint2* dp = (uint2*)(Bs + o*LDH + ch*64);
        #pragma unroll
        for (int i = 0; i < 16; i++) dp[i] = wp[i];
    }
    __syncthreads();

    const int w = tid >> 5, wr = w >> 1, wc = w & 1;
    #pragma unroll
    for (int i = 0; i < 2; i++) {
        FragC acc[4];
        #pragma unroll
        for (int jj = 0; jj < 4; jj++) wmma::fill_fragment(acc[jj], 0.f);
        #pragma unroll
        for (int k = 0; k < 8; k++) {
            FragA a; wmma::load_matrix_sync(a, As + (wr*32 + i*16)*LDH + k*16, LDH);
            #pragma unroll
            for (int jj = 0; jj < 4; jj++) {
                FragBc bfr; wmma::load_matrix_sync(bfr, Bs + (wc*64 + jj*16)*LDH + k*16, LDH);
                wmma::mma_sync(acc[jj], a, bfr, acc[jj]);
            }
        }
        #pragma unroll
        for (int jj = 0; jj < 4; jj++)
            wmma::store_matrix_sync(Cs + (wr*32 + i*16)*LDF + wc*64 + jj*16, acc[jj], LDF, wmma::mem_row_major);
    }
    __syncthreads();
    // out[b][c][n] = x + proj + bias  (transposed write, coalesced over n)
    {
        int c = tid >> 1, nh = tid & 1;
        const float* xp = x + ((size_t)(b*CC) + c)*NN + nbase + nh*64;
        float* op = out + ((size_t)(b*CC) + c)*NN + nbase + nh*64;
        float pb = projb[c];
        #pragma unroll
        for (int i = 0; i < 64; i++)
            op[i] = xp[i] + pb + Cs[(nh*64 + i)*LDF + c];
    }
}

// ---------------- launcher ----------------
extern "C" void kernel_launch(void* const* d_in, const int* in_sizes, int n_in,
                              void* d_out, int out_size) {
    const float* x     = (const float*)d_in[0];
    const float* nw    = (const float*)d_in[1];
    const float* nb    = (const float*)d_in[2];
    const float* qkvw  = (const float*)d_in[3];
    const float* qkvb  = (const float*)d_in[4];
    const float* projw = (const float*)d_in[5];
    const float* projb = (const float*)d_in[6];
    float* out = (float*)d_out;

    const int SM_GEMM = 2*128*LDH*2 + 128*LDF*4;                       // 137216
    const int SM_ATTN = 4*128*LDH*2 + 128*LDF*4 + (128 + 256)*4;       // 208384

    cudaFuncSetAttribute(k_qkv,  cudaFuncAttributeMaxDynamicSharedMemorySize, SM_GEMM);
    cudaFuncSetAttribute(k_attn, cudaFuncAttributeMaxDynamicSharedMemorySize, SM_ATTN);
    cudaFuncSetAttribute(k_proj, cudaFuncAttributeMaxDynamicSharedMemorySize, SM_GEMM);

    k_convert<<<192, 256>>>(qkvw, projw);
    k_gnstats<<<32, 256>>>(x, nw, nb);
    k_qkv<<<dim3(32, BB), 256, SM_GEMM>>>(x, qkvb);
    k_attn<<<dim3(32, BB), 256, SM_ATTN>>>();
    k_proj<<<dim3(32, BB), 256, SM_GEMM>>>(x, projb, out);
}